// round 4
// baseline (speedup 1.0000x reference)
#include <cuda_runtime.h>

// Problem constants (fixed by the dataset)
#define BS 8
#define NQ 1500
#define NPRED (BS * NQ)   // 12000
#define NTGT 4800
#define BJ 128            // targets per block tile (32 lanes x 4 j)
#define PRW 12            // preds per warp
#define BI (8 * PRW)      // 96 preds per block; 12000 % 96 == 0

// C[i,j] = 5*|px_i - tx_j| + 5*|py_i - ty_j| + sp_i - t0_j*x0_i - t1_j*x1_i
// sp_i = softplus(x0_i) + softplus(x1_i)

__global__ __launch_bounds__(256, 8)
void hungarian_cost_kernel(const float* __restrict__ pred_logits,
                           const float* __restrict__ pred_points,
                           const float* __restrict__ tgt_labels,
                           const float* __restrict__ tgt_points,
                           float* __restrict__ out)
{
    __shared__ float  s_tx[BJ], s_ty[BJ], s_t0[BJ], s_t1[BJ];  // target SoA (scaled)
    __shared__ float4 s_pred[BI];   // {5*px, 5*py, -x0, -x1}
    __shared__ float  s_sp[BI];     // softplus sum per pred

    const int lane   = threadIdx.x;
    const int w      = threadIdx.y;          // warp id 0..7
    const int tid    = w * 32 + lane;
    const int j_base = blockIdx.x * BJ;
    const int i_base = blockIdx.y * BI;

    // ---- Prologue (disjoint thread ranges, single pass) ----
    if (tid < BJ) {
        // stage target tile, coalesced
        const int jt = j_base + tid;
        float2 p = make_float2(0.f, 0.f), l2 = make_float2(0.f, 0.f);
        if (jt < NTGT) {
            p  = ((const float2*)tgt_points)[jt];
            l2 = ((const float2*)tgt_labels)[jt];
        }
        s_tx[tid] = 5.0f * p.x;
        s_ty[tid] = 5.0f * p.y;
        s_t0[tid] = l2.x;
        s_t1[tid] = l2.y;
    } else if (tid < BJ + BI) {
        // stage pred state (softplus computed once per pred per block)
        const int i = i_base + (tid - BJ);   // always < NPRED
        const float2 x = ((const float2*)pred_logits)[i];
        const float2 p = ((const float2*)pred_points)[i];
        const float sp = fmaxf(x.x, 0.f) + log1pf(expf(-fabsf(x.x)))
                       + fmaxf(x.y, 0.f) + log1pf(expf(-fabsf(x.y)));
        s_pred[tid - BJ] = make_float4(5.0f * p.x, 5.0f * p.y, -x.x, -x.y);
        s_sp[tid - BJ]   = sp;
    }

    __syncthreads();

    const int j0 = j_base + lane * 4;
    if (j0 >= NTGT) return;   // partial last j-tile (4800 % 128 = 64)

    // ---- Hoist this lane's 4 targets: conflict-free LDS.128 from SoA ----
    const float4 vtx = ((const float4*)s_tx)[lane];
    const float4 vty = ((const float4*)s_ty)[lane];
    const float4 vt0 = ((const float4*)s_t0)[lane];
    const float4 vt1 = ((const float4*)s_t1)[lane];

    float* const obase = out + (size_t)(i_base + w * PRW) * NTGT + j0;

    // ---- Main loop: 12 preds per warp, broadcast pred state, streaming stores ----
    #pragma unroll
    for (int pl = 0; pl < PRW; pl++) {
        const float4 pr = s_pred[w * PRW + pl];   // broadcast LDS.128
        const float  sp = s_sp[w * PRW + pl];     // broadcast LDS.32

        float4 r;
        {
            const float s = fabsf(pr.x - vtx.x) + fabsf(pr.y - vty.x);
            r.x = s + fmaf(vt1.x, pr.w, fmaf(vt0.x, pr.z, sp));
        }
        {
            const float s = fabsf(pr.x - vtx.y) + fabsf(pr.y - vty.y);
            r.y = s + fmaf(vt1.y, pr.w, fmaf(vt0.y, pr.z, sp));
        }
        {
            const float s = fabsf(pr.x - vtx.z) + fabsf(pr.y - vty.z);
            r.z = s + fmaf(vt1.z, pr.w, fmaf(vt0.z, pr.z, sp));
        }
        {
            const float s = fabsf(pr.x - vtx.w) + fabsf(pr.y - vty.w);
            r.w = s + fmaf(vt1.w, pr.w, fmaf(vt0.w, pr.z, sp));
        }
        __stcs((float4*)(obase + (size_t)pl * NTGT), r);   // evict-first streaming store
    }
}

extern "C" void kernel_launch(void* const* d_in, const int* in_sizes, int n_in,
                              void* d_out, int out_size)
{
    const float* pred_logits = (const float*)d_in[0];  // (8,1500,2)
    const float* pred_points = (const float*)d_in[1];  // (8,1500,2)
    const float* tgt_labels  = (const float*)d_in[2];  // (4800,2)
    const float* tgt_points  = (const float*)d_in[3];  // (4800,2)
    float* out = (float*)d_out;                        // (8,1500,4800)

    dim3 block(32, 8);
    dim3 grid((NTGT + BJ - 1) / BJ, NPRED / BI);       // (38, 125)
    hungarian_cost_kernel<<<grid, block>>>(pred_logits, pred_points,
                                           tgt_labels, tgt_points, out);
}

// round 5
// speedup vs baseline: 1.0653x; 1.0653x over previous
#include <cuda_runtime.h>

// Problem constants (fixed by the dataset)
#define BS 8
#define NQ 1500
#define NPRED (BS * NQ)   // 12000
#define NTGT 4800
#define BJ 128            // targets per block tile (32 lanes x 4 j)
#define PRW 12            // preds per warp
#define BI (8 * PRW)      // 96 preds per block; 12000 % 96 == 0

// C[i,j] = 5*|px_i - tx_j| + 5*|py_i - ty_j| + sp_i - t0_j*x0_i - t1_j*x1_i
// sp_i = softplus(x0_i) + softplus(x1_i)

__global__ __launch_bounds__(256, 6)
void hungarian_cost_kernel(const float* __restrict__ pred_logits,
                           const float* __restrict__ pred_points,
                           const float* __restrict__ tgt_labels,
                           const float* __restrict__ tgt_points,
                           float* __restrict__ out)
{
    __shared__ float  s_tx[BJ], s_ty[BJ], s_t0[BJ], s_t1[BJ];  // target SoA (scaled)
    __shared__ float4 s_pred[BI];   // {5*px, 5*py, x0, x1}
    __shared__ float  s_sp[BI];     // softplus sum

    const int lane   = threadIdx.x;
    const int w      = threadIdx.y;          // warp id 0..7
    const int tid    = w * 32 + lane;
    const int j_base = blockIdx.x * BJ;
    const int i_base = blockIdx.y * BI;

    // ---- Prologue (disjoint thread ranges, single pass) ----
    if (tid < BJ) {
        // stage target tile, coalesced
        const int jt = j_base + tid;
        float2 p = make_float2(0.f, 0.f), l2 = make_float2(0.f, 0.f);
        if (jt < NTGT) {
            p  = ((const float2*)tgt_points)[jt];
            l2 = ((const float2*)tgt_labels)[jt];
        }
        s_tx[tid] = 5.0f * p.x;
        s_ty[tid] = 5.0f * p.y;
        s_t0[tid] = l2.x;
        s_t1[tid] = l2.y;
    } else if (tid < BJ + BI) {
        // stage pred state (softplus computed once per pred per block)
        const int i = i_base + (tid - BJ);   // always < NPRED
        const float2 x = ((const float2*)pred_logits)[i];
        const float2 p = ((const float2*)pred_points)[i];
        const float sp = fmaxf(x.x, 0.f) + log1pf(expf(-fabsf(x.x)))
                       + fmaxf(x.y, 0.f) + log1pf(expf(-fabsf(x.y)));
        s_pred[tid - BJ] = make_float4(5.0f * p.x, 5.0f * p.y, x.x, x.y);
        s_sp[tid - BJ]   = sp;
    }

    __syncthreads();

    const int j0 = j_base + lane * 4;
    if (j0 >= NTGT) return;   // partial last j-tile (4800 % 128 = 64)

    // ---- Hoist this lane's 4 targets: conflict-free LDS.128 from SoA ----
    const float4 vtx = ((const float4*)s_tx)[lane];
    const float4 vty = ((const float4*)s_ty)[lane];
    const float4 vt0 = ((const float4*)s_t0)[lane];
    const float4 vt1 = ((const float4*)s_t1)[lane];

    float* const obase = out + (size_t)(i_base + w * PRW) * NTGT + j0;

    // ---- Main loop: 12 preds per warp, broadcast pred state ----
    #pragma unroll
    for (int p4 = 0; p4 < PRW / 4; p4++) {
        const float4 sp4 = ((const float4*)s_sp)[w * (PRW / 4) + p4];  // broadcast
        #pragma unroll
        for (int q = 0; q < 4; q++) {
            const int    pl = p4 * 4 + q;                 // pred within warp
            const float4 pr = s_pred[w * PRW + pl];       // broadcast LDS.128
            const float  sp = (q == 0) ? sp4.x : (q == 1) ? sp4.y
                            : (q == 2) ? sp4.z : sp4.w;

            float4 r;
            {
                const float s = fabsf(pr.x - vtx.x) + fabsf(pr.y - vty.x);
                float e = fmaf(-vt0.x, pr.z, sp);
                e       = fmaf(-vt1.x, pr.w, e);
                r.x = s + e;
            }
            {
                const float s = fabsf(pr.x - vtx.y) + fabsf(pr.y - vty.y);
                float e = fmaf(-vt0.y, pr.z, sp);
                e       = fmaf(-vt1.y, pr.w, e);
                r.y = s + e;
            }
            {
                const float s = fabsf(pr.x - vtx.z) + fabsf(pr.y - vty.z);
                float e = fmaf(-vt0.z, pr.z, sp);
                e       = fmaf(-vt1.z, pr.w, e);
                r.z = s + e;
            }
            {
                const float s = fabsf(pr.x - vtx.w) + fabsf(pr.y - vty.w);
                float e = fmaf(-vt0.w, pr.z, sp);
                e       = fmaf(-vt1.w, pr.w, e);
                r.w = s + e;
            }
            __stcs((float4*)(obase + (size_t)pl * NTGT), r);  // streaming store (evict-first)
        }
    }
}

extern "C" void kernel_launch(void* const* d_in, const int* in_sizes, int n_in,
                              void* d_out, int out_size)
{
    const float* pred_logits = (const float*)d_in[0];  // (8,1500,2)
    const float* pred_points = (const float*)d_in[1];  // (8,1500,2)
    const float* tgt_labels  = (const float*)d_in[2];  // (4800,2)
    const float* tgt_points  = (const float*)d_in[3];  // (4800,2)
    float* out = (float*)d_out;                        // (8,1500,4800)

    dim3 block(32, 8);
    dim3 grid((NTGT + BJ - 1) / BJ, NPRED / BI);       // (38, 125)
    hungarian_cost_kernel<<<grid, block>>>(pred_logits, pred_points,
                                           tgt_labels, tgt_points, out);
}